// round 15
// baseline (speedup 1.0000x reference)
#include <cuda_runtime.h>
#include <cuda_fp16.h>
#include <cstdint>

#define M_TOTAL 32768
#define E_DIM   512
#define FFN_DIM 2048

#if defined(__CUDA_ARCH__) && defined(__CUDA_ARCH_FEAT_SM103_ALL)
#define HAS_TCGEN05 1
#else
#define HAS_TCGEN05 0
#endif

// scratch (device globals, allocation-free)
__device__ float g_x1[(size_t)M_TOTAL * E_DIM];   // LN1 out
__device__ float g_fq[(size_t)M_TOTAL * 8];       // cos(x1[:, :8] + theta_ffn)
// packed weights: fp16, SW128 smem image, 64KB per 512x64 k-tile
__device__ uint4 g_Wcp[32768];                    // Wc: 8 tiles x 64KB = 512KB
__device__ uint4 g_W2p[131072];                   // W2: 32 tiles x 64KB = 2MB

// ---------------- smem layout (dynamic) ----------------
#define SM_TMEM   0
#define MB_FULL0  16
#define MB_FULL1  24
#define MB_EMPTY0 32
#define MB_EMPTY1 40
#define MB_FIN    48
#define SM_RED    64          // 512 floats
#define SM_PAR    2112        // 3 x 512 floats (bias, gamma, beta)
#define SM_TH     8256        // gemm1: theta 2KB / gemm2: fq 4KB
#define SM_A0     16384       // 16KB (128 rows x 128B, 64 fp16/row)
#define SM_A1     32768       // 16KB
#define SM_B0     49152       // 64KB (512 rows x 128B)
#define SM_B1     114688      // 64KB
#define SMEM_BYTES 180224
#define SM_EP     16384       // epilogue bounce (reuses A/B space post-mainloop)

// idesc kind::f16 fp16: dtype=F32(1<<4), N=128(16<<17), M=128(8<<24)
#define IDESC_F16 ((1u<<4)|(16u<<17)|(8u<<24))

// ---------------- common helpers (all PTX stages) ----------------
__device__ __forceinline__ uint32_t smem_u32(const void* p) {
    uint32_t a;
    asm("{ .reg .u64 t; cvta.to.shared.u64 t, %1; cvt.u32.u64 %0, t; }" : "=r"(a) : "l"(p));
    return a;
}
__device__ __forceinline__ uint32_t f2h2(float a, float b) {
    __half2 h = __floats2half2_rn(a, b);
    return *(uint32_t*)&h;
}
// swizzled byte offset of 16B group q16 within row (128B rows, SW128)
__device__ __forceinline__ uint32_t swz_off(int row, int q16) {
    return (uint32_t)(row * 128 + ((q16 ^ (row & 7)) * 16));
}

// ================= weight repack (fp32 -> fp16 SW128 image) =================
__global__ __launch_bounds__(256) void repack_kernel(const float* __restrict__ src,
                                                     int K, int which) {
    uint4* dst = which ? g_W2p : g_Wcp;
    const int g = blockIdx.x * blockDim.x + threadIdx.x;   // one 16B group = 8 fp16
    const int total = 512 * K / 8;
    if (g >= total) return;
    const int q16 = g & 7;
    const int row = (g >> 3) & 511;
    const int tile = g >> 12;
    const float* s = src + (size_t)row * K + tile * 64 + q16 * 8;
    const float4 v0 = *(const float4*)s;
    const float4 v1 = *(const float4*)(s + 4);
    uint4 o;
    o.x = f2h2(v0.x, v0.y); o.y = f2h2(v0.z, v0.w);
    o.z = f2h2(v1.x, v1.y); o.w = f2h2(v1.z, v1.w);
    *(uint4*)((char*)dst + (size_t)tile * 65536 + swz_off(row, q16)) = o;
}

#if HAS_TCGEN05
// ---------------- tcgen05 helpers (sm_103a only) ----------------
__device__ __forceinline__ uint32_t elect_one() {
    uint32_t p;
    asm volatile("{ .reg .pred p; elect.sync _|p, 0xFFFFFFFF; selp.b32 %0, 1, 0, p; }" : "=r"(p));
    return p;
}
__device__ __forceinline__ uint64_t make_desc(uint32_t addr) {
    return (uint64_t(2) << 61) | (uint64_t(1) << 46) | (uint64_t(64) << 32) |
           (uint64_t(1) << 16) | ((addr >> 4) & 0x3FFFu);
}
__device__ __forceinline__ void mma_f16(uint32_t d, uint64_t ad, uint64_t bd,
                                        uint32_t idesc, uint32_t en) {
    asm volatile(
        "{\n\t.reg .pred p;\n\tsetp.ne.u32 p, %5, 0;\n\t"
        "tcgen05.mma.cta_group::1.kind::f16 [%0], %1, %2, %3, {%4, %4, %4, %4}, p;\n\t}"
        :: "r"(d), "l"(ad), "l"(bd), "r"(idesc), "r"(0u), "r"(en) : "memory");
}
__device__ __forceinline__ void tc_commit(uint32_t mbar) {
    asm volatile(
        "tcgen05.commit.cta_group::1.mbarrier::arrive::one.shared::cluster.b64 [%0];"
        :: "r"(mbar) : "memory");
}
__device__ __forceinline__ void mbar_init(uint32_t mbar, uint32_t cnt) {
    asm volatile("mbarrier.init.shared.b64 [%0], %1;" :: "r"(mbar), "r"(cnt) : "memory");
}
__device__ __forceinline__ void mbar_arrive(uint32_t mbar) {
    asm volatile("mbarrier.arrive.shared.b64 _, [%0];" :: "r"(mbar) : "memory");
}
__device__ __forceinline__ void mbar_wait(uint32_t mbar, uint32_t ph) {
    asm volatile(
        "{\n\t.reg .pred P1;\n\t"
        "W_%=:\n\t"
        "mbarrier.try_wait.parity.acquire.cta.shared::cta.b64 P1, [%0], %1, 0x989680;\n\t"
        "@P1 bra D_%=;\n\t"
        "bra W_%=;\n\t"
        "D_%=:\n\t}"
        :: "r"(mbar), "r"(ph) : "memory");
}
__device__ __forceinline__ void fence_proxy_async_cta() {
    asm volatile("fence.proxy.async.shared::cta;" ::: "memory");
}
__device__ __forceinline__ void tc_fence_after() {
    asm volatile("tcgen05.fence::after_thread_sync;" ::: "memory");
}
// cp.async (LDGSTS)
__device__ __forceinline__ void cp16(uint32_t dst, const void* src) {
    asm volatile("cp.async.cg.shared.global [%0], [%1], 16;" :: "r"(dst), "l"(src) : "memory");
}
#define CP_COMMIT() asm volatile("cp.async.commit_group;" ::: "memory")
#define CP_WAIT(n)  asm volatile("cp.async.wait_group %0;" :: "n"(n) : "memory")

#define TC_ALLOC(dst, n)   asm volatile("tcgen05.alloc.cta_group::1.sync.aligned.shared::cta.b32 [%0], %1;" :: "r"(dst), "r"(n) : "memory")
#define TC_RELINQ()        asm volatile("tcgen05.relinquish_alloc_permit.cta_group::1.sync.aligned;")
#define TC_DEALLOC(t, n)   asm volatile("tcgen05.dealloc.cta_group::1.sync.aligned.b32 %0, %1;" :: "r"(t), "r"(n))
#define TC_WAIT_LD()       asm volatile("tcgen05.wait::ld.sync.aligned;" ::: "memory")
#define LDTM_X32(r, a) \
    asm volatile("tcgen05.ld.sync.aligned.32x32b.x32.b32 " \
        "{%0,%1,%2,%3,%4,%5,%6,%7,%8,%9,%10,%11,%12,%13,%14,%15," \
        "%16,%17,%18,%19,%20,%21,%22,%23,%24,%25,%26,%27,%28,%29,%30,%31}, [%32];" \
        : "=r"((r)[0]),"=r"((r)[1]),"=r"((r)[2]),"=r"((r)[3]),"=r"((r)[4]),"=r"((r)[5]),"=r"((r)[6]),"=r"((r)[7]), \
          "=r"((r)[8]),"=r"((r)[9]),"=r"((r)[10]),"=r"((r)[11]),"=r"((r)[12]),"=r"((r)[13]),"=r"((r)[14]),"=r"((r)[15]), \
          "=r"((r)[16]),"=r"((r)[17]),"=r"((r)[18]),"=r"((r)[19]),"=r"((r)[20]),"=r"((r)[21]),"=r"((r)[22]),"=r"((r)[23]), \
          "=r"((r)[24]),"=r"((r)[25]),"=r"((r)[26]),"=r"((r)[27]),"=r"((r)[28]),"=r"((r)[29]),"=r"((r)[30]),"=r"((r)[31]) \
        : "r"(a))

// MMA issue for one 128x512x64 fp16 tile (4 ksteps x 4 nchunks); commit -> mbar
__device__ __forceinline__ void issue_tile(uint32_t sb, uint32_t a_off, uint32_t b_off,
                                           uint32_t tmem, bool first, uint32_t mbar) {
    const uint64_t ab = make_desc(sb + a_off);
    const uint64_t bb = make_desc(sb + b_off);
    if (elect_one()) {
#pragma unroll
        for (int ks = 0; ks < 4; ++ks) {
            const uint32_t en = (!first || ks > 0) ? 1u : 0u;
#pragma unroll
            for (int nc = 0; nc < 4; ++nc)
                mma_f16(tmem + nc * 128, ab + ks * 2, bb + nc * 1024 + ks * 2,
                        IDESC_F16, en);
        }
        tc_commit(mbar);
    }
}

// Fused epilogue: y = D + resid + bias; LN(y) -> dst; optionally fq from cols 0..7.
__device__ __forceinline__ void epilogue_ln(char* sm, uint32_t tmem,
                                            const float* __restrict__ resid,
                                            float* __restrict__ dst, int bm, int t,
                                            bool do_fq, const float* __restrict__ thF) {
    const int w = t >> 5, lane = t & 31;
    const int sp = w & 3, half = w >> 2;
    const int row_local = sp * 32 + lane;
    const int grow = bm + row_local;
    const float* xr = resid + (size_t)grow * E_DIM;
    const float* bias = (const float*)(sm + SM_PAR);
    const float* gam  = (const float*)(sm + SM_PAR + 2048);
    const float* bet  = (const float*)(sm + SM_PAR + 4096);
    float* redp = (float*)(sm + SM_RED);

    // pass 1: stats
    float s = 0.f, ss = 0.f;
#pragma unroll 1
    for (int ch = 0; ch < 8; ++ch) {
        const int colb = half * 256 + ch * 32;
        uint32_t r[32];
        LDTM_X32(r, tmem + colb);
        TC_WAIT_LD();
#pragma unroll
        for (int c4 = 0; c4 < 8; ++c4) {
            const float4 xv = *(const float4*)(xr + colb + c4 * 4);
            const float4 bv = *(const float4*)(bias + colb + c4 * 4);
            float y0 = __uint_as_float(r[c4 * 4 + 0]) + xv.x + bv.x;
            float y1 = __uint_as_float(r[c4 * 4 + 1]) + xv.y + bv.y;
            float y2 = __uint_as_float(r[c4 * 4 + 2]) + xv.z + bv.z;
            float y3 = __uint_as_float(r[c4 * 4 + 3]) + xv.w + bv.w;
            s += y0 + y1 + y2 + y3;
            ss = fmaf(y0, y0, fmaf(y1, y1, fmaf(y2, y2, fmaf(y3, y3, ss))));
        }
    }
    redp[row_local * 2 + half] = s;
    redp[256 + row_local * 2 + half] = ss;
    __syncthreads();
    const float st  = redp[row_local * 2] + redp[row_local * 2 + 1];
    const float sst = redp[256 + row_local * 2] + redp[256 + row_local * 2 + 1];
    const float mu  = st * (1.0f / 512.0f);
    const float inv = rsqrtf(sst * (1.0f / 512.0f) - mu * mu + 1e-5f);

    // pass 2: normalize + store (coalesced via bounce)
    float* eb = (float*)(sm + SM_EP + w * 4608);  // [32][36]
    const int rbase = sp * 32;
#pragma unroll 1
    for (int ch = 0; ch < 8; ++ch) {
        const int colb = half * 256 + ch * 32;
        uint32_t r[32];
        LDTM_X32(r, tmem + colb);
        TC_WAIT_LD();
#pragma unroll
        for (int c4 = 0; c4 < 8; ++c4) {
            const float4 xv = *(const float4*)(xr + colb + c4 * 4);
            const float4 bv = *(const float4*)(bias + colb + c4 * 4);
            const float4 gv = *(const float4*)(gam + colb + c4 * 4);
            const float4 tv = *(const float4*)(bet + colb + c4 * 4);
            float4 o;
            o.x = (__uint_as_float(r[c4 * 4 + 0]) + xv.x + bv.x - mu) * inv * gv.x + tv.x;
            o.y = (__uint_as_float(r[c4 * 4 + 1]) + xv.y + bv.y - mu) * inv * gv.y + tv.y;
            o.z = (__uint_as_float(r[c4 * 4 + 2]) + xv.z + bv.z - mu) * inv * gv.z + tv.z;
            o.w = (__uint_as_float(r[c4 * 4 + 3]) + xv.w + bv.w - mu) * inv * gv.w + tv.w;
            *(float4*)(eb + lane * 36 + c4 * 4) = o;
        }
        if (do_fq && half == 0 && ch == 0) {
            const float4 o0 = *(const float4*)(eb + lane * 36);
            const float4 o1 = *(const float4*)(eb + lane * 36 + 4);
            float4 c0, c1;
            c0.x = __cosf(o0.x + thF[0]); c0.y = __cosf(o0.y + thF[1]);
            c0.z = __cosf(o0.z + thF[2]); c0.w = __cosf(o0.w + thF[3]);
            c1.x = __cosf(o1.x + thF[4]); c1.y = __cosf(o1.y + thF[5]);
            c1.z = __cosf(o1.z + thF[6]); c1.w = __cosf(o1.w + thF[7]);
            *(float4*)(g_fq + (size_t)grow * 8) = c0;
            *(float4*)(g_fq + (size_t)grow * 8 + 4) = c1;
        }
        __syncwarp();
#pragma unroll
        for (int j = 0; j < 32; ++j)
            dst[(size_t)(bm + rbase + j) * E_DIM + colb + lane] = eb[j * 36 + lane];
        __syncwarp();
    }
}
#endif  // HAS_TCGEN05

// ================= GEMM1 + LN1 fused (inline cos A-gen) =================
__global__ __launch_bounds__(256, 1)
void gemm1_tc(const float* __restrict__ x, const float* __restrict__ theta,
              const float* __restrict__ bc, const float* __restrict__ g1,
              const float* __restrict__ be1, const float* __restrict__ thF) {
#if HAS_TCGEN05
    extern __shared__ char sm[];
    const uint32_t sb = smem_u32(sm);
    const int t = threadIdx.x;
    const int bm = blockIdx.x * 128;

    if (t < 32) TC_ALLOC(sb + SM_TMEM, 512);
    if (t == 0) {
        mbar_init(sb + MB_FULL0, 224);  mbar_init(sb + MB_FULL1, 224);
        mbar_init(sb + MB_EMPTY0, 1);   mbar_init(sb + MB_EMPTY1, 1);
        mbar_init(sb + MB_FIN, 1);
    }
    ((float*)(sm + SM_PAR))[t] = bc[t];          ((float*)(sm + SM_PAR))[t + 256] = bc[t + 256];
    ((float*)(sm + SM_PAR + 2048))[t] = g1[t];   ((float*)(sm + SM_PAR + 2048))[t + 256] = g1[t + 256];
    ((float*)(sm + SM_PAR + 4096))[t] = be1[t];  ((float*)(sm + SM_PAR + 4096))[t + 256] = be1[t + 256];
    ((float*)(sm + SM_TH))[t] = theta[t];        ((float*)(sm + SM_TH))[t + 256] = theta[t + 256];
    __syncthreads();

    uint32_t tmem;
    asm volatile("ld.shared.b32 %0, [%1];" : "=r"(tmem) : "r"(sb + SM_TMEM));
    const float* th_s = (const float*)(sm + SM_TH);
    const char* bsrc = (const char*)g_Wcp;
    const int NIT = E_DIM / 64;  // 8

    if (t < 32) {
        // ---- MMA warp ----
        int phf[2] = {0, 0};
        for (int it = 0; it < NIT; ++it) {
            const int s = it & 1;
            mbar_wait(sb + MB_FULL0 + s * 8, phf[s]); phf[s] ^= 1;
            issue_tile(sb, s ? SM_A1 : SM_A0, s ? SM_B1 : SM_B0, tmem, it == 0,
                       sb + MB_EMPTY0 + s * 8);
        }
        if (elect_one()) tc_commit(sb + MB_FIN);
    } else {
        // ---- producers (224 threads) ----
        const int pt = t - 32;
        auto copyB = [&](int it) {
            const char* bs = bsrc + (size_t)it * 65536;
            const uint32_t d = sb + ((it & 1) ? SM_B1 : SM_B0);
            for (int g = pt; g < 4096; g += 224)
                cp16(d + g * 16, bs + (size_t)g * 16);
            CP_COMMIT();
        };
        auto genA = [&](int it, uint32_t Aoff) {
            const int k0 = it * 64;
            for (int idx = pt; idx < 1024; idx += 224) {
                const int row = idx >> 3, q16 = idx & 7;
                const float* xp = x + (size_t)(bm + row) * E_DIM + k0 + q16 * 8;
                const float4 v0 = *(const float4*)xp;
                const float4 v1 = *(const float4*)(xp + 4);
                const float4 t0 = *(const float4*)(th_s + k0 + q16 * 8);
                const float4 t1 = *(const float4*)(th_s + k0 + q16 * 8 + 4);
                uint4 o;
                o.x = f2h2(__cosf(v0.x + t0.x), __cosf(v0.y + t0.y));
                o.y = f2h2(__cosf(v0.z + t0.z), __cosf(v0.w + t0.w));
                o.z = f2h2(__cosf(v1.x + t1.x), __cosf(v1.y + t1.y));
                o.w = f2h2(__cosf(v1.z + t1.z), __cosf(v1.w + t1.w));
                *(uint4*)(sm + Aoff + swz_off(row, q16)) = o;
            }
        };

        // prologue
        copyB(0);
        CP_WAIT(0);
        genA(0, SM_A0);
        fence_proxy_async_cta();
        mbar_arrive(sb + MB_FULL0);
        copyB(1);  // flies during MMA(0)

        int phe[2] = {0, 0};
        for (int it = 1; it < NIT; ++it) {
            const int s = it & 1;
            CP_WAIT(0);                       // B(it) landed
            if (it + 1 < NIT) {               // issue copy(it+1) BEFORE genA(it)
                const int s2 = (it + 1) & 1;
                mbar_wait(sb + MB_EMPTY0 + s2 * 8, phe[s2]); phe[s2] ^= 1;
                copyB(it + 1);
            }
            genA(it, s ? SM_A1 : SM_A0);      // overlaps copy(it+1) flight
            fence_proxy_async_cta();
            mbar_arrive(sb + MB_FULL0 + s * 8);
        }
    }

    mbar_wait(sb + MB_FIN, 0);
    tc_fence_after();
    __syncthreads();

    epilogue_ln(sm, tmem, x, g_x1, bm, t, true, thF);

    __syncthreads();
    if (t < 32) { TC_RELINQ(); TC_DEALLOC(tmem, 512); }
#endif
}

// ================= GEMM2 + LN2 fused (inline h A-gen, register W1) =========
__global__ __launch_bounds__(256, 1)
void gemm2_tc(const float* __restrict__ W1, const float* __restrict__ b1,
              const float* __restrict__ b2, const float* __restrict__ g2,
              const float* __restrict__ be2, float* __restrict__ out) {
#if HAS_TCGEN05
    extern __shared__ char sm[];
    const uint32_t sb = smem_u32(sm);
    const int t = threadIdx.x;
    const int bm = blockIdx.x * 128;

    if (t < 32) TC_ALLOC(sb + SM_TMEM, 512);
    if (t == 0) {
        mbar_init(sb + MB_FULL0, 224);  mbar_init(sb + MB_FULL1, 224);
        mbar_init(sb + MB_EMPTY0, 1);   mbar_init(sb + MB_EMPTY1, 1);
        mbar_init(sb + MB_FIN, 1);
    }
    ((float*)(sm + SM_PAR))[t] = b2[t];          ((float*)(sm + SM_PAR))[t + 256] = b2[t + 256];
    ((float*)(sm + SM_PAR + 2048))[t] = g2[t];   ((float*)(sm + SM_PAR + 2048))[t + 256] = g2[t + 256];
    ((float*)(sm + SM_PAR + 4096))[t] = be2[t];  ((float*)(sm + SM_PAR + 4096))[t + 256] = be2[t + 256];
    ((float4*)(sm + SM_TH))[t] = ((const float4*)(g_fq + (size_t)bm * 8))[t];  // fq 4KB
    __syncthreads();

    uint32_t tmem;
    asm volatile("ld.shared.b32 %0, [%1];" : "=r"(tmem) : "r"(sb + SM_TMEM));
    const char* bsrc = (const char*)g_W2p;
    const int NIT = FFN_DIM / 64;  // 32

    if (t < 32) {
        // ---- MMA warp ----
        int phf[2] = {0, 0};
        for (int it = 0; it < NIT; ++it) {
            const int s = it & 1;
            mbar_wait(sb + MB_FULL0 + s * 8, phf[s]); phf[s] ^= 1;
            issue_tile(sb, s ? SM_A1 : SM_A0, s ? SM_B1 : SM_B0, tmem, it == 0,
                       sb + MB_EMPTY0 + s * 8);
        }
        if (elect_one()) tc_commit(sb + MB_FIN);
    } else {
        // ---- producers (224 threads): q16 = k-octet 0..7, rgrp = row group 0..27
        const int pt = t - 32;
        const int q16 = pt & 7;
        const int rgrp = pt >> 3;
        auto copyB = [&](int it) {
            const char* bs = bsrc + (size_t)it * 65536;
            const uint32_t d = sb + ((it & 1) ? SM_B1 : SM_B0);
            for (int g = pt; g < 4096; g += 224)
                cp16(d + g * 16, bs + (size_t)g * 16);
            CP_COMMIT();
        };
        // h = relu(b1 + fq.W1) for this thread's 8 k-values, rows rgrp..127 step 28.
        // W1 rows held in registers (L2-resident LDG); fq reads are broadcast-class.
        auto genA = [&](int it, uint32_t Aoff) {
            const int kb = it * 64 + q16 * 8;
            float w[8][8];
            float bb[8];
#pragma unroll
            for (int j = 0; j < 8; ++j) {
                const float4 a = *(const float4*)(W1 + (size_t)(kb + j) * 8);
                const float4 b = *(const float4*)(W1 + (size_t)(kb + j) * 8 + 4);
                w[j][0] = a.x; w[j][1] = a.y; w[j][2] = a.z; w[j][3] = a.w;
                w[j][4] = b.x; w[j][5] = b.y; w[j][6] = b.z; w[j][7] = b.w;
                bb[j] = b1[kb + j];
            }
#pragma unroll 1
            for (int r = rgrp; r < 128; r += 28) {
                const float4 f0 = *(const float4*)(sm + SM_TH + r * 32);
                const float4 f1 = *(const float4*)(sm + SM_TH + r * 32 + 16);
                float h[8];
#pragma unroll
                for (int j = 0; j < 8; ++j) {
                    float s = bb[j];
                    s = fmaf(f0.x, w[j][0], s); s = fmaf(f0.y, w[j][1], s);
                    s = fmaf(f0.z, w[j][2], s); s = fmaf(f0.w, w[j][3], s);
                    s = fmaf(f1.x, w[j][4], s); s = fmaf(f1.y, w[j][5], s);
                    s = fmaf(f1.z, w[j][6], s); s = fmaf(f1.w, w[j][7], s);
                    h[j] = fmaxf(s, 0.0f);
                }
                uint4 o;
                o.x = f2h2(h[0], h[1]); o.y = f2h2(h[2], h[3]);
                o.z = f2h2(h[4], h[5]); o.w = f2h2(h[6], h[7]);
                *(uint4*)(sm + Aoff + swz_off(r, q16)) = o;
            }
        };

        // prologue
        copyB(0);
        CP_WAIT(0);
        genA(0, SM_A0);
        fence_proxy_async_cta();
        mbar_arrive(sb + MB_FULL0);
        copyB(1);

        int phe[2] = {0, 0};
        for (int it = 1; it < NIT; ++it) {
            const int s = it & 1;
            CP_WAIT(0);
            if (it + 1 < NIT) {
                const int s2 = (it + 1) & 1;
                mbar_wait(sb + MB_EMPTY0 + s2 * 8, phe[s2]); phe[s2] ^= 1;
                copyB(it + 1);
            }
            genA(it, s ? SM_A1 : SM_A0);
            fence_proxy_async_cta();
            mbar_arrive(sb + MB_FULL0 + s * 8);
        }
    }

    mbar_wait(sb + MB_FIN, 0);
    tc_fence_after();
    __syncthreads();

    epilogue_ln(sm, tmem, g_x1, out, bm, t, false, nullptr);

    __syncthreads();
    if (t < 32) { TC_RELINQ(); TC_DEALLOC(tmem, 512); }
#endif
}

// ================= launch =================
extern "C" void kernel_launch(void* const* d_in, const int* in_sizes, int n_in,
                              void* d_out, int out_size) {
    const float* x   = (const float*)d_in[0];
    const float* thA = (const float*)d_in[1];
    const float* Wc  = (const float*)d_in[2];
    const float* bc  = (const float*)d_in[3];
    const float* g1  = (const float*)d_in[4];
    const float* be1 = (const float*)d_in[5];
    const float* thF = (const float*)d_in[6];
    const float* W1  = (const float*)d_in[7];
    const float* b1  = (const float*)d_in[8];
    const float* W2  = (const float*)d_in[9];
    const float* b2  = (const float*)d_in[10];
    const float* g2  = (const float*)d_in[11];
    const float* be2 = (const float*)d_in[12];
    float* out = (float*)d_out;

    cudaFuncSetAttribute(gemm1_tc, cudaFuncAttributeMaxDynamicSharedMemorySize, SMEM_BYTES);
    cudaFuncSetAttribute(gemm2_tc, cudaFuncAttributeMaxDynamicSharedMemorySize, SMEM_BYTES);

    // pack weights (fp16 + SW128 smem image)
    repack_kernel<<<(512 * E_DIM / 8 + 255) / 256, 256>>>(Wc, E_DIM, 0);
    repack_kernel<<<(512 * FFN_DIM / 8 + 255) / 256, 256>>>(W2, FFN_DIM, 1);

    gemm1_tc<<<M_TOTAL / 128, 256, SMEM_BYTES>>>(x, thA, bc, g1, be1, thF);
    gemm2_tc<<<M_TOTAL / 128, 256, SMEM_BYTES>>>(W1, b1, b2, g2, be2, out);
}

// round 16
// speedup vs baseline: 1.3275x; 1.3275x over previous
#include <cuda_runtime.h>
#include <cuda_fp16.h>
#include <cstdint>

#define M_TOTAL 32768
#define E_DIM   512
#define FFN_DIM 2048

#if defined(__CUDA_ARCH__) && defined(__CUDA_ARCH_FEAT_SM103_ALL)
#define HAS_TCGEN05 1
#else
#define HAS_TCGEN05 0
#endif

// scratch (device globals, allocation-free)
__device__ float g_x1[(size_t)M_TOTAL * E_DIM];   // LN1 out
__device__ float g_fq[(size_t)M_TOTAL * 8];       // cos(x1[:, :8] + theta_ffn)
// packed weights: fp16, SW128 smem image, 64KB per 512x64 k-tile
__device__ uint4 g_Wcp[32768];                    // Wc: 8 tiles x 64KB = 512KB
__device__ uint4 g_W2p[131072];                   // W2: 32 tiles x 64KB = 2MB

// ---------------- smem layout (dynamic) ----------------
#define SM_TMEM   0
#define MB_FULL0  16
#define MB_FULL1  24
#define MB_EMPTY0 32
#define MB_EMPTY1 40
#define MB_FIN    48
#define SM_RED    64          // 512 floats
#define SM_PAR    2112        // 3 x 512 floats (bias, gamma, beta)
#define SM_TH     8256        // gemm1: theta 2KB / gemm2: fq 4KB
#define SM_A0     16384       // 16KB (128 rows x 128B, 64 fp16/row)
#define SM_A1     32768       // 16KB
#define SM_B0     49152       // 64KB (512 rows x 128B)
#define SM_B1     114688      // 64KB
#define SMEM_BYTES 180224
#define SM_EP     16384       // epilogue bounce (reuses A/B space post-mainloop)

// idesc kind::f16 fp16: dtype=F32(1<<4), N=128(16<<17), M=128(8<<24)
#define IDESC_F16 ((1u<<4)|(16u<<17)|(8u<<24))

// ---------------- common helpers (all PTX stages) ----------------
__device__ __forceinline__ uint32_t smem_u32(const void* p) {
    uint32_t a;
    asm("{ .reg .u64 t; cvta.to.shared.u64 t, %1; cvt.u32.u64 %0, t; }" : "=r"(a) : "l"(p));
    return a;
}
__device__ __forceinline__ uint32_t f2h2(float a, float b) {
    __half2 h = __floats2half2_rn(a, b);
    return *(uint32_t*)&h;
}
// swizzled byte offset of 16B group q16 within row (128B rows, SW128)
__device__ __forceinline__ uint32_t swz_off(int row, int q16) {
    return (uint32_t)(row * 128 + ((q16 ^ (row & 7)) * 16));
}

// ================= weight repack (fp32 -> fp16 SW128 image) =================
__global__ __launch_bounds__(256) void repack_kernel(const float* __restrict__ src,
                                                     int K, int which) {
    uint4* dst = which ? g_W2p : g_Wcp;
    const int g = blockIdx.x * blockDim.x + threadIdx.x;   // one 16B group = 8 fp16
    const int total = 512 * K / 8;
    if (g >= total) return;
    const int q16 = g & 7;
    const int row = (g >> 3) & 511;
    const int tile = g >> 12;
    const float* s = src + (size_t)row * K + tile * 64 + q16 * 8;
    const float4 v0 = *(const float4*)s;
    const float4 v1 = *(const float4*)(s + 4);
    uint4 o;
    o.x = f2h2(v0.x, v0.y); o.y = f2h2(v0.z, v0.w);
    o.z = f2h2(v1.x, v1.y); o.w = f2h2(v1.z, v1.w);
    *(uint4*)((char*)dst + (size_t)tile * 65536 + swz_off(row, q16)) = o;
}

#if HAS_TCGEN05
// ---------------- tcgen05 helpers (sm_103a only) ----------------
__device__ __forceinline__ uint32_t elect_one() {
    uint32_t p;
    asm volatile("{ .reg .pred p; elect.sync _|p, 0xFFFFFFFF; selp.b32 %0, 1, 0, p; }" : "=r"(p));
    return p;
}
__device__ __forceinline__ uint64_t make_desc(uint32_t addr) {
    return (uint64_t(2) << 61) | (uint64_t(1) << 46) | (uint64_t(64) << 32) |
           (uint64_t(1) << 16) | ((addr >> 4) & 0x3FFFu);
}
__device__ __forceinline__ void mma_f16(uint32_t d, uint64_t ad, uint64_t bd,
                                        uint32_t idesc, uint32_t en) {
    asm volatile(
        "{\n\t.reg .pred p;\n\tsetp.ne.u32 p, %5, 0;\n\t"
        "tcgen05.mma.cta_group::1.kind::f16 [%0], %1, %2, %3, {%4, %4, %4, %4}, p;\n\t}"
        :: "r"(d), "l"(ad), "l"(bd), "r"(idesc), "r"(0u), "r"(en) : "memory");
}
__device__ __forceinline__ void tc_commit(uint32_t mbar) {
    asm volatile(
        "tcgen05.commit.cta_group::1.mbarrier::arrive::one.shared::cluster.b64 [%0];"
        :: "r"(mbar) : "memory");
}
__device__ __forceinline__ void mbar_init(uint32_t mbar, uint32_t cnt) {
    asm volatile("mbarrier.init.shared.b64 [%0], %1;" :: "r"(mbar), "r"(cnt) : "memory");
}
__device__ __forceinline__ void mbar_arrive(uint32_t mbar) {
    asm volatile("mbarrier.arrive.shared.b64 _, [%0];" :: "r"(mbar) : "memory");
}
__device__ __forceinline__ void mbar_wait(uint32_t mbar, uint32_t ph) {
    asm volatile(
        "{\n\t.reg .pred P1;\n\t"
        "W_%=:\n\t"
        "mbarrier.try_wait.parity.acquire.cta.shared::cta.b64 P1, [%0], %1, 0x989680;\n\t"
        "@P1 bra D_%=;\n\t"
        "bra W_%=;\n\t"
        "D_%=:\n\t}"
        :: "r"(mbar), "r"(ph) : "memory");
}
__device__ __forceinline__ void fence_proxy_async_cta() {
    asm volatile("fence.proxy.async.shared::cta;" ::: "memory");
}
__device__ __forceinline__ void tc_fence_after() {
    asm volatile("tcgen05.fence::after_thread_sync;" ::: "memory");
}
// cp.async (LDGSTS)
__device__ __forceinline__ void cp16(uint32_t dst, const void* src) {
    asm volatile("cp.async.cg.shared.global [%0], [%1], 16;" :: "r"(dst), "l"(src) : "memory");
}
#define CP_COMMIT() asm volatile("cp.async.commit_group;" ::: "memory")
#define CP_WAIT(n)  asm volatile("cp.async.wait_group %0;" :: "n"(n) : "memory")

#define TC_ALLOC(dst, n)   asm volatile("tcgen05.alloc.cta_group::1.sync.aligned.shared::cta.b32 [%0], %1;" :: "r"(dst), "r"(n) : "memory")
#define TC_RELINQ()        asm volatile("tcgen05.relinquish_alloc_permit.cta_group::1.sync.aligned;")
#define TC_DEALLOC(t, n)   asm volatile("tcgen05.dealloc.cta_group::1.sync.aligned.b32 %0, %1;" :: "r"(t), "r"(n))
#define TC_WAIT_LD()       asm volatile("tcgen05.wait::ld.sync.aligned;" ::: "memory")
#define LDTM_X32(r, a) \
    asm volatile("tcgen05.ld.sync.aligned.32x32b.x32.b32 " \
        "{%0,%1,%2,%3,%4,%5,%6,%7,%8,%9,%10,%11,%12,%13,%14,%15," \
        "%16,%17,%18,%19,%20,%21,%22,%23,%24,%25,%26,%27,%28,%29,%30,%31}, [%32];" \
        : "=r"((r)[0]),"=r"((r)[1]),"=r"((r)[2]),"=r"((r)[3]),"=r"((r)[4]),"=r"((r)[5]),"=r"((r)[6]),"=r"((r)[7]), \
          "=r"((r)[8]),"=r"((r)[9]),"=r"((r)[10]),"=r"((r)[11]),"=r"((r)[12]),"=r"((r)[13]),"=r"((r)[14]),"=r"((r)[15]), \
          "=r"((r)[16]),"=r"((r)[17]),"=r"((r)[18]),"=r"((r)[19]),"=r"((r)[20]),"=r"((r)[21]),"=r"((r)[22]),"=r"((r)[23]), \
          "=r"((r)[24]),"=r"((r)[25]),"=r"((r)[26]),"=r"((r)[27]),"=r"((r)[28]),"=r"((r)[29]),"=r"((r)[30]),"=r"((r)[31]) \
        : "r"(a))

// MMA issue for one 128x512x64 fp16 tile (4 ksteps x 4 nchunks); commit -> mbar
__device__ __forceinline__ void issue_tile(uint32_t sb, uint32_t a_off, uint32_t b_off,
                                           uint32_t tmem, bool first, uint32_t mbar) {
    const uint64_t ab = make_desc(sb + a_off);
    const uint64_t bb = make_desc(sb + b_off);
    if (elect_one()) {
#pragma unroll
        for (int ks = 0; ks < 4; ++ks) {
            const uint32_t en = (!first || ks > 0) ? 1u : 0u;
#pragma unroll
            for (int nc = 0; nc < 4; ++nc)
                mma_f16(tmem + nc * 128, ab + ks * 2, bb + nc * 1024 + ks * 2,
                        IDESC_F16, en);
        }
        tc_commit(mbar);
    }
}

// Fused epilogue: y = D + resid + bias; LN(y) -> dst; optionally fq from cols 0..7.
__device__ __forceinline__ void epilogue_ln(char* sm, uint32_t tmem,
                                            const float* __restrict__ resid,
                                            float* __restrict__ dst, int bm, int t,
                                            bool do_fq, const float* __restrict__ thF) {
    const int w = t >> 5, lane = t & 31;
    const int sp = w & 3, half = w >> 2;
    const int row_local = sp * 32 + lane;
    const int grow = bm + row_local;
    const float* xr = resid + (size_t)grow * E_DIM;
    const float* bias = (const float*)(sm + SM_PAR);
    const float* gam  = (const float*)(sm + SM_PAR + 2048);
    const float* bet  = (const float*)(sm + SM_PAR + 4096);
    float* redp = (float*)(sm + SM_RED);

    // pass 1: stats
    float s = 0.f, ss = 0.f;
#pragma unroll 1
    for (int ch = 0; ch < 8; ++ch) {
        const int colb = half * 256 + ch * 32;
        uint32_t r[32];
        LDTM_X32(r, tmem + colb);
        TC_WAIT_LD();
#pragma unroll
        for (int c4 = 0; c4 < 8; ++c4) {
            const float4 xv = *(const float4*)(xr + colb + c4 * 4);
            const float4 bv = *(const float4*)(bias + colb + c4 * 4);
            float y0 = __uint_as_float(r[c4 * 4 + 0]) + xv.x + bv.x;
            float y1 = __uint_as_float(r[c4 * 4 + 1]) + xv.y + bv.y;
            float y2 = __uint_as_float(r[c4 * 4 + 2]) + xv.z + bv.z;
            float y3 = __uint_as_float(r[c4 * 4 + 3]) + xv.w + bv.w;
            s += y0 + y1 + y2 + y3;
            ss = fmaf(y0, y0, fmaf(y1, y1, fmaf(y2, y2, fmaf(y3, y3, ss))));
        }
    }
    redp[row_local * 2 + half] = s;
    redp[256 + row_local * 2 + half] = ss;
    __syncthreads();
    const float st  = redp[row_local * 2] + redp[row_local * 2 + 1];
    const float sst = redp[256 + row_local * 2] + redp[256 + row_local * 2 + 1];
    const float mu  = st * (1.0f / 512.0f);
    const float inv = rsqrtf(sst * (1.0f / 512.0f) - mu * mu + 1e-5f);

    // pass 2: normalize + store (coalesced via bounce)
    float* eb = (float*)(sm + SM_EP + w * 4608);  // [32][36]
    const int rbase = sp * 32;
#pragma unroll 1
    for (int ch = 0; ch < 8; ++ch) {
        const int colb = half * 256 + ch * 32;
        uint32_t r[32];
        LDTM_X32(r, tmem + colb);
        TC_WAIT_LD();
#pragma unroll
        for (int c4 = 0; c4 < 8; ++c4) {
            const float4 xv = *(const float4*)(xr + colb + c4 * 4);
            const float4 bv = *(const float4*)(bias + colb + c4 * 4);
            const float4 gv = *(const float4*)(gam + colb + c4 * 4);
            const float4 tv = *(const float4*)(bet + colb + c4 * 4);
            float4 o;
            o.x = (__uint_as_float(r[c4 * 4 + 0]) + xv.x + bv.x - mu) * inv * gv.x + tv.x;
            o.y = (__uint_as_float(r[c4 * 4 + 1]) + xv.y + bv.y - mu) * inv * gv.y + tv.y;
            o.z = (__uint_as_float(r[c4 * 4 + 2]) + xv.z + bv.z - mu) * inv * gv.z + tv.z;
            o.w = (__uint_as_float(r[c4 * 4 + 3]) + xv.w + bv.w - mu) * inv * gv.w + tv.w;
            *(float4*)(eb + lane * 36 + c4 * 4) = o;
        }
        if (do_fq && half == 0 && ch == 0) {
            const float4 o0 = *(const float4*)(eb + lane * 36);
            const float4 o1 = *(const float4*)(eb + lane * 36 + 4);
            float4 c0, c1;
            c0.x = __cosf(o0.x + thF[0]); c0.y = __cosf(o0.y + thF[1]);
            c0.z = __cosf(o0.z + thF[2]); c0.w = __cosf(o0.w + thF[3]);
            c1.x = __cosf(o1.x + thF[4]); c1.y = __cosf(o1.y + thF[5]);
            c1.z = __cosf(o1.z + thF[6]); c1.w = __cosf(o1.w + thF[7]);
            *(float4*)(g_fq + (size_t)grow * 8) = c0;
            *(float4*)(g_fq + (size_t)grow * 8 + 4) = c1;
        }
        __syncwarp();
#pragma unroll
        for (int j = 0; j < 32; ++j)
            dst[(size_t)(bm + rbase + j) * E_DIM + colb + lane] = eb[j * 36 + lane];
        __syncwarp();
    }
}
#endif  // HAS_TCGEN05

// ================= GEMM1 + LN1 fused (fp16, warp-specialized) =================
__global__ __launch_bounds__(256, 1)
void gemm1_tc(const float* __restrict__ x, const float* __restrict__ theta,
              const float* __restrict__ bc, const float* __restrict__ g1,
              const float* __restrict__ be1, const float* __restrict__ thF) {
#if HAS_TCGEN05
    extern __shared__ char sm[];
    const uint32_t sb = smem_u32(sm);
    const int t = threadIdx.x;
    const int bm = blockIdx.x * 128;

    if (t < 32) TC_ALLOC(sb + SM_TMEM, 512);
    if (t == 0) {
        mbar_init(sb + MB_FULL0, 224);  mbar_init(sb + MB_FULL1, 224);
        mbar_init(sb + MB_EMPTY0, 1);   mbar_init(sb + MB_EMPTY1, 1);
        mbar_init(sb + MB_FIN, 1);
    }
    ((float*)(sm + SM_PAR))[t] = bc[t];          ((float*)(sm + SM_PAR))[t + 256] = bc[t + 256];
    ((float*)(sm + SM_PAR + 2048))[t] = g1[t];   ((float*)(sm + SM_PAR + 2048))[t + 256] = g1[t + 256];
    ((float*)(sm + SM_PAR + 4096))[t] = be1[t];  ((float*)(sm + SM_PAR + 4096))[t + 256] = be1[t + 256];
    ((float*)(sm + SM_TH))[t] = theta[t];        ((float*)(sm + SM_TH))[t + 256] = theta[t + 256];
    __syncthreads();

    uint32_t tmem;
    asm volatile("ld.shared.b32 %0, [%1];" : "=r"(tmem) : "r"(sb + SM_TMEM));
    const float* th_s = (const float*)(sm + SM_TH);
    const char* bsrc = (const char*)g_Wcp;
    const int NIT = E_DIM / 64;  // 8

    if (t < 32) {
        // ---- MMA warp ----
        int phf[2] = {0, 0};
        for (int it = 0; it < NIT; ++it) {
            const int s = it & 1;
            mbar_wait(sb + MB_FULL0 + s * 8, phf[s]); phf[s] ^= 1;
            issue_tile(sb, s ? SM_A1 : SM_A0, s ? SM_B1 : SM_B0, tmem, it == 0,
                       sb + MB_EMPTY0 + s * 8);
        }
        if (elect_one()) tc_commit(sb + MB_FIN);
    } else {
        // ---- producers (224 threads) ----
        const int pt = t - 32;
        auto copyB = [&](int it) {
            const char* bs = bsrc + (size_t)it * 65536;
            const uint32_t d = sb + ((it & 1) ? SM_B1 : SM_B0);
            for (int g = pt; g < 4096; g += 224)
                cp16(d + g * 16, bs + (size_t)g * 16);
            CP_COMMIT();
        };
        auto genA = [&](int it, uint32_t Aoff) {
            const int k0 = it * 64;
            for (int idx = pt; idx < 1024; idx += 224) {
                const int row = idx >> 3, q16 = idx & 7;
                const float* xp = x + (size_t)(bm + row) * E_DIM + k0 + q16 * 8;
                const float4 v0 = *(const float4*)xp;
                const float4 v1 = *(const float4*)(xp + 4);
                const float4 t0 = *(const float4*)(th_s + k0 + q16 * 8);
                const float4 t1 = *(const float4*)(th_s + k0 + q16 * 8 + 4);
                uint4 o;
                o.x = f2h2(__cosf(v0.x + t0.x), __cosf(v0.y + t0.y));
                o.y = f2h2(__cosf(v0.z + t0.z), __cosf(v0.w + t0.w));
                o.z = f2h2(__cosf(v1.x + t1.x), __cosf(v1.y + t1.y));
                o.w = f2h2(__cosf(v1.z + t1.z), __cosf(v1.w + t1.w));
                *(uint4*)(sm + Aoff + swz_off(row, q16)) = o;
            }
        };

        // prologue
        copyB(0);
        CP_WAIT(0);
        genA(0, SM_A0);
        fence_proxy_async_cta();
        mbar_arrive(sb + MB_FULL0);
        copyB(1);   // flies during MMA(0)

        int phe[2] = {0, 0};
        for (int it = 1; it < NIT; ++it) {
            const int s = it & 1;
            CP_WAIT(0);                         // B(it) landed (long in flight)
            if (it + 1 < NIT) {                 // issue copy(it+1) BEFORE genA(it)
                const int s2 = (it + 1) & 1;
                mbar_wait(sb + MB_EMPTY0 + s2 * 8, phe[s2]); phe[s2] ^= 1;
                copyB(it + 1);
            }
            genA(it, s ? SM_A1 : SM_A0);        // overlaps copy(it+1) flight
            fence_proxy_async_cta();
            mbar_arrive(sb + MB_FULL0 + s * 8);
        }
    }

    mbar_wait(sb + MB_FIN, 0);
    tc_fence_after();
    __syncthreads();

    epilogue_ln(sm, tmem, x, g_x1, bm, t, true, thF);

    __syncthreads();
    if (t < 32) { TC_RELINQ(); TC_DEALLOC(tmem, 512); }
#endif
}

// ================= GEMM2 + LN2 fused (fp16, warp-specialized) =================
__global__ __launch_bounds__(256, 1)
void gemm2_tc(const float* __restrict__ W1, const float* __restrict__ b1,
              const float* __restrict__ b2, const float* __restrict__ g2,
              const float* __restrict__ be2, float* __restrict__ out) {
#if HAS_TCGEN05
    extern __shared__ char sm[];
    const uint32_t sb = smem_u32(sm);
    const int t = threadIdx.x;
    const int bm = blockIdx.x * 128;

    if (t < 32) TC_ALLOC(sb + SM_TMEM, 512);
    if (t == 0) {
        mbar_init(sb + MB_FULL0, 224);  mbar_init(sb + MB_FULL1, 224);
        mbar_init(sb + MB_EMPTY0, 1);   mbar_init(sb + MB_EMPTY1, 1);
        mbar_init(sb + MB_FIN, 1);
    }
    ((float*)(sm + SM_PAR))[t] = b2[t];          ((float*)(sm + SM_PAR))[t + 256] = b2[t + 256];
    ((float*)(sm + SM_PAR + 2048))[t] = g2[t];   ((float*)(sm + SM_PAR + 2048))[t + 256] = g2[t + 256];
    ((float*)(sm + SM_PAR + 4096))[t] = be2[t];  ((float*)(sm + SM_PAR + 4096))[t + 256] = be2[t + 256];
    ((float4*)(sm + SM_TH))[t] = ((const float4*)(g_fq + (size_t)bm * 8))[t];  // fq 4KB
    __syncthreads();

    uint32_t tmem;
    asm volatile("ld.shared.b32 %0, [%1];" : "=r"(tmem) : "r"(sb + SM_TMEM));
    const char* bsrc = (const char*)g_W2p;
    const int NIT = FFN_DIM / 64;  // 32

    if (t < 32) {
        // ---- MMA warp ----
        int phf[2] = {0, 0};
        for (int it = 0; it < NIT; ++it) {
            const int s = it & 1;
            mbar_wait(sb + MB_FULL0 + s * 8, phf[s]); phf[s] ^= 1;
            issue_tile(sb, s ? SM_A1 : SM_A0, s ? SM_B1 : SM_B0, tmem, it == 0,
                       sb + MB_EMPTY0 + s * 8);
        }
        if (elect_one()) tc_commit(sb + MB_FIN);
    } else {
        // ---- producers (224 threads): kl = k-col-pair 0..31, rg = row group 0..6 ----
        const int pt = t - 32;
        const int kl = pt & 31;      // handles k columns 2*kl, 2*kl+1 of the tile
        const int rg = pt >> 5;      // row group 0..6
        auto copyB = [&](int it) {
            const char* bs = bsrc + (size_t)it * 65536;
            const uint32_t d = sb + ((it & 1) ? SM_B1 : SM_B0);
            for (int g = pt; g < 4096; g += 224)
                cp16(d + g * 16, bs + (size_t)g * 16);
            CP_COMMIT();
        };
        // prefetch W1/b1 rows for tile `it` into registers (R12-proven)
        float4 wa0, wa1, wb0, wb1;
        float s0, s1;
        auto prefW = [&](int it) {
            const int k = it * 64 + kl * 2;
            wa0 = *(const float4*)(W1 + (size_t)k * 8);
            wa1 = *(const float4*)(W1 + (size_t)k * 8 + 4);
            wb0 = *(const float4*)(W1 + (size_t)(k + 1) * 8);
            wb1 = *(const float4*)(W1 + (size_t)(k + 1) * 8 + 4);
            s0 = b1[k]; s1 = b1[k + 1];
        };
        // A tile: h = relu(b1 + fq.W1) for 2 k-cols, rows rg..127 step 7
        auto genA = [&](uint32_t Aoff) {
            const uint32_t inner = (uint32_t)((kl & 3) * 4);
            const uint32_t q16g = (uint32_t)(kl >> 2);
#pragma unroll 2
            for (int r = rg; r < 128; r += 7) {
                const float4 f0 = *(const float4*)(sm + SM_TH + r * 32);
                const float4 f1 = *(const float4*)(sm + SM_TH + r * 32 + 16);
                float h0 = s0, h1 = s1;
                h0 = fmaf(f0.x, wa0.x, h0); h0 = fmaf(f0.y, wa0.y, h0);
                h0 = fmaf(f0.z, wa0.z, h0); h0 = fmaf(f0.w, wa0.w, h0);
                h0 = fmaf(f1.x, wa1.x, h0); h0 = fmaf(f1.y, wa1.y, h0);
                h0 = fmaf(f1.z, wa1.z, h0); h0 = fmaf(f1.w, wa1.w, h0);
                h1 = fmaf(f0.x, wb0.x, h1); h1 = fmaf(f0.y, wb0.y, h1);
                h1 = fmaf(f0.z, wb0.z, h1); h1 = fmaf(f0.w, wb0.w, h1);
                h1 = fmaf(f1.x, wb1.x, h1); h1 = fmaf(f1.y, wb1.y, h1);
                h1 = fmaf(f1.z, wb1.z, h1); h1 = fmaf(f1.w, wb1.w, h1);
                h0 = fmaxf(h0, 0.0f); h1 = fmaxf(h1, 0.0f);
                *(uint32_t*)(sm + Aoff + (uint32_t)(r * 128) +
                             (((q16g ^ (uint32_t)(r & 7)) * 16) + inner)) = f2h2(h0, h1);
            }
        };

        // prologue
        prefW(0);
        copyB(0);
        CP_WAIT(0);
        genA(SM_A0);
        fence_proxy_async_cta();
        mbar_arrive(sb + MB_FULL0);
        prefW(1);
        copyB(1);   // flies during MMA(0)

        int phe[2] = {0, 0};
        for (int it = 1; it < NIT; ++it) {
            const int s = it & 1;
            CP_WAIT(0);                          // B(it) landed (long in flight)
            if (it + 1 < NIT) {                  // issue copy(it+1) BEFORE genA(it)
                const int s2 = (it + 1) & 1;
                mbar_wait(sb + MB_EMPTY0 + s2 * 8, phe[s2]); phe[s2] ^= 1;
                copyB(it + 1);
            }
            genA(s ? SM_A1 : SM_A0);             // uses W regs prefetched last iter
            fence_proxy_async_cta();
            mbar_arrive(sb + MB_FULL0 + s * 8);
            if (it + 1 < NIT) prefW(it + 1);     // W LDGs fly during next CP_WAIT
        }
    }

    mbar_wait(sb + MB_FIN, 0);
    tc_fence_after();
    __syncthreads();

    epilogue_ln(sm, tmem, g_x1, out, bm, t, false, nullptr);

    __syncthreads();
    if (t < 32) { TC_RELINQ(); TC_DEALLOC(tmem, 512); }
#endif
}

// ================= launch =================
extern "C" void kernel_launch(void* const* d_in, const int* in_sizes, int n_in,
                              void* d_out, int out_size) {
    const float* x   = (const float*)d_in[0];
    const float* thA = (const float*)d_in[1];
    const float* Wc  = (const float*)d_in[2];
    const float* bc  = (const float*)d_in[3];
    const float* g1  = (const float*)d_in[4];
    const float* be1 = (const float*)d_in[5];
    const float* thF = (const float*)d_in[6];
    const float* W1  = (const float*)d_in[7];
    const float* b1  = (const float*)d_in[8];
    const float* W2  = (const float*)d_in[9];
    const float* b2  = (const float*)d_in[10];
    const float* g2  = (const float*)d_in[11];
    const float* be2 = (const float*)d_in[12];
    float* out = (float*)d_out;

    cudaFuncSetAttribute(gemm1_tc, cudaFuncAttributeMaxDynamicSharedMemorySize, SMEM_BYTES);
    cudaFuncSetAttribute(gemm2_tc, cudaFuncAttributeMaxDynamicSharedMemorySize, SMEM_BYTES);

    // pack weights (fp16 + SW128 smem image)
    repack_kernel<<<(512 * E_DIM / 8 + 255) / 256, 256>>>(Wc, E_DIM, 0);
    repack_kernel<<<(512 * FFN_DIM / 8 + 255) / 256, 256>>>(W2, FFN_DIM, 1);

    gemm1_tc<<<M_TOTAL / 128, 256, SMEM_BYTES>>>(x, thA, bc, g1, be1, thF);
    gemm2_tc<<<M_TOTAL / 128, 256, SMEM_BYTES>>>(W1, b1, b2, g2, be2, out);
}

// round 17
// speedup vs baseline: 1.4209x; 1.0704x over previous
#include <cuda_runtime.h>
#include <cuda_fp16.h>
#include <cstdint>

#define M_TOTAL 32768
#define E_DIM   512
#define FFN_DIM 2048

#if defined(__CUDA_ARCH__) && defined(__CUDA_ARCH_FEAT_SM103_ALL)
#define HAS_TCGEN05 1
#else
#define HAS_TCGEN05 0
#endif

// scratch (device globals, allocation-free)
__device__ float g_x1[(size_t)M_TOTAL * E_DIM];   // LN1 out
__device__ float g_fq[(size_t)M_TOTAL * 8];       // cos(x1[:, :8] + theta_ffn)
// packed weights: fp16, SW128 smem image, 64KB per 512x64 k-tile
__device__ uint4 g_Wcp[32768];                    // Wc: 8 tiles x 64KB = 512KB
__device__ uint4 g_W2p[131072];                   // W2: 32 tiles x 64KB = 2MB

// ---------------- smem layout (dynamic) ----------------
#define SM_TMEM   0
#define MB_FA     16     // fullA stages 0..3 (count 224): 16,24,32,40
#define MB_FB     48     // fullB stages 0..1 (count 256): 48,56
#define MB_EA     64     // emptyA stages 0..3 (commit): 64,72,80,88
#define MB_EB     96     // emptyB stages 0..1 (commit): 96,104
#define MB_FIN    112
#define SM_RED    128        // 1024 floats (s,ss x 128 rows x 4 quarters)
#define SM_PAR    4224       // 3 x 512 floats (bias, gamma, beta)
#define SM_TH     10368      // gemm1: theta 2KB / gemm2: fq 4KB
#define SM_A0     16384      // 4 stages x 16KB: 16384..81920
#define SM_B0     81920      // 2 stages x 64KB: 81920..212992
#define SMEM_BYTES 212992
#define SM_EP     16384      // epilogue bounce (16 warps x 4608 = 72KB, reuses A/B)

// idesc kind::f16 fp16: dtype=F32(1<<4), N=128(16<<17), M=128(8<<24)
#define IDESC_F16 ((1u<<4)|(16u<<17)|(8u<<24))

// ---------------- common helpers (all PTX stages) ----------------
__device__ __forceinline__ uint32_t smem_u32(const void* p) {
    uint32_t a;
    asm("{ .reg .u64 t; cvta.to.shared.u64 t, %1; cvt.u32.u64 %0, t; }" : "=r"(a) : "l"(p));
    return a;
}
__device__ __forceinline__ uint32_t f2h2(float a, float b) {
    __half2 h = __floats2half2_rn(a, b);
    return *(uint32_t*)&h;
}
// swizzled byte offset of 16B group q16 within row (128B rows, SW128)
__device__ __forceinline__ uint32_t swz_off(int row, int q16) {
    return (uint32_t)(row * 128 + ((q16 ^ (row & 7)) * 16));
}

// ================= weight repack (fp32 -> fp16 SW128 image) =================
__global__ __launch_bounds__(256) void repack_kernel(const float* __restrict__ src,
                                                     int K, int which) {
    uint4* dst = which ? g_W2p : g_Wcp;
    const int g = blockIdx.x * blockDim.x + threadIdx.x;   // one 16B group = 8 fp16
    const int total = 512 * K / 8;
    if (g >= total) return;
    const int q16 = g & 7;
    const int row = (g >> 3) & 511;
    const int tile = g >> 12;
    const float* s = src + (size_t)row * K + tile * 64 + q16 * 8;
    const float4 v0 = *(const float4*)s;
    const float4 v1 = *(const float4*)(s + 4);
    uint4 o;
    o.x = f2h2(v0.x, v0.y); o.y = f2h2(v0.z, v0.w);
    o.z = f2h2(v1.x, v1.y); o.w = f2h2(v1.z, v1.w);
    *(uint4*)((char*)dst + (size_t)tile * 65536 + swz_off(row, q16)) = o;
}

#if HAS_TCGEN05
// ---------------- tcgen05 helpers (sm_103a only) ----------------
__device__ __forceinline__ uint32_t elect_one() {
    uint32_t p;
    asm volatile("{ .reg .pred p; elect.sync _|p, 0xFFFFFFFF; selp.b32 %0, 1, 0, p; }" : "=r"(p));
    return p;
}
__device__ __forceinline__ uint64_t make_desc(uint32_t addr) {
    return (uint64_t(2) << 61) | (uint64_t(1) << 46) | (uint64_t(64) << 32) |
           (uint64_t(1) << 16) | ((addr >> 4) & 0x3FFFu);
}
__device__ __forceinline__ void mma_f16(uint32_t d, uint64_t ad, uint64_t bd,
                                        uint32_t idesc, uint32_t en) {
    asm volatile(
        "{\n\t.reg .pred p;\n\tsetp.ne.u32 p, %5, 0;\n\t"
        "tcgen05.mma.cta_group::1.kind::f16 [%0], %1, %2, %3, {%4, %4, %4, %4}, p;\n\t}"
        :: "r"(d), "l"(ad), "l"(bd), "r"(idesc), "r"(0u), "r"(en) : "memory");
}
__device__ __forceinline__ void tc_commit(uint32_t mbar) {
    asm volatile(
        "tcgen05.commit.cta_group::1.mbarrier::arrive::one.shared::cluster.b64 [%0];"
        :: "r"(mbar) : "memory");
}
__device__ __forceinline__ void mbar_init(uint32_t mbar, uint32_t cnt) {
    asm volatile("mbarrier.init.shared.b64 [%0], %1;" :: "r"(mbar), "r"(cnt) : "memory");
}
__device__ __forceinline__ void mbar_arrive(uint32_t mbar) {
    asm volatile("mbarrier.arrive.shared.b64 _, [%0];" :: "r"(mbar) : "memory");
}
__device__ __forceinline__ void mbar_wait(uint32_t mbar, uint32_t ph) {
    asm volatile(
        "{\n\t.reg .pred P1;\n\t"
        "W_%=:\n\t"
        "mbarrier.try_wait.parity.acquire.cta.shared::cta.b64 P1, [%0], %1, 0x989680;\n\t"
        "@P1 bra D_%=;\n\t"
        "bra W_%=;\n\t"
        "D_%=:\n\t}"
        :: "r"(mbar), "r"(ph) : "memory");
}
__device__ __forceinline__ void fence_proxy_async_cta() {
    asm volatile("fence.proxy.async.shared::cta;" ::: "memory");
}
__device__ __forceinline__ void tc_fence_after() {
    asm volatile("tcgen05.fence::after_thread_sync;" ::: "memory");
}
// cp.async (LDGSTS)
__device__ __forceinline__ void cp16(uint32_t dst, const void* src) {
    asm volatile("cp.async.cg.shared.global [%0], [%1], 16;" :: "r"(dst), "l"(src) : "memory");
}
#define CP_COMMIT() asm volatile("cp.async.commit_group;" ::: "memory")
#define CP_WAIT(n)  asm volatile("cp.async.wait_group %0;" :: "n"(n) : "memory")

#define TC_ALLOC(dst, n)   asm volatile("tcgen05.alloc.cta_group::1.sync.aligned.shared::cta.b32 [%0], %1;" :: "r"(dst), "r"(n) : "memory")
#define TC_RELINQ()        asm volatile("tcgen05.relinquish_alloc_permit.cta_group::1.sync.aligned;")
#define TC_DEALLOC(t, n)   asm volatile("tcgen05.dealloc.cta_group::1.sync.aligned.b32 %0, %1;" :: "r"(t), "r"(n))
#define TC_WAIT_LD()       asm volatile("tcgen05.wait::ld.sync.aligned;" ::: "memory")
#define LDTM_X32(r, a) \
    asm volatile("tcgen05.ld.sync.aligned.32x32b.x32.b32 " \
        "{%0,%1,%2,%3,%4,%5,%6,%7,%8,%9,%10,%11,%12,%13,%14,%15," \
        "%16,%17,%18,%19,%20,%21,%22,%23,%24,%25,%26,%27,%28,%29,%30,%31}, [%32];" \
        : "=r"((r)[0]),"=r"((r)[1]),"=r"((r)[2]),"=r"((r)[3]),"=r"((r)[4]),"=r"((r)[5]),"=r"((r)[6]),"=r"((r)[7]), \
          "=r"((r)[8]),"=r"((r)[9]),"=r"((r)[10]),"=r"((r)[11]),"=r"((r)[12]),"=r"((r)[13]),"=r"((r)[14]),"=r"((r)[15]), \
          "=r"((r)[16]),"=r"((r)[17]),"=r"((r)[18]),"=r"((r)[19]),"=r"((r)[20]),"=r"((r)[21]),"=r"((r)[22]),"=r"((r)[23]), \
          "=r"((r)[24]),"=r"((r)[25]),"=r"((r)[26]),"=r"((r)[27]),"=r"((r)[28]),"=r"((r)[29]),"=r"((r)[30]),"=r"((r)[31]) \
        : "r"(a))

// MMA issue for one 128x512x64 fp16 tile (4 ksteps x 4 nchunks); dual commits
__device__ __forceinline__ void issue_tile(uint32_t sb, uint32_t a_off, uint32_t b_off,
                                           uint32_t tmem, bool first,
                                           uint32_t mbarB, uint32_t mbarA) {
    const uint64_t ab = make_desc(sb + a_off);
    const uint64_t bb = make_desc(sb + b_off);
    if (elect_one()) {
#pragma unroll
        for (int ks = 0; ks < 4; ++ks) {
            const uint32_t en = (!first || ks > 0) ? 1u : 0u;
#pragma unroll
            for (int nc = 0; nc < 4; ++nc)
                mma_f16(tmem + nc * 128, ab + ks * 2, bb + nc * 1024 + ks * 2,
                        IDESC_F16, en);
        }
        tc_commit(mbarB);
        tc_commit(mbarA);
    }
}

// Fused epilogue (16 warps): y = D + resid + bias; LN(y) -> dst; optional fq.
__device__ __forceinline__ void epilogue_ln(char* sm, uint32_t tmem,
                                            const float* __restrict__ resid,
                                            float* __restrict__ dst, int bm, int t,
                                            bool do_fq, const float* __restrict__ thF) {
    const int w = t >> 5, lane = t & 31;
    const int sp = w & 3, q = w >> 2;           // row quarter, col quarter
    const int row_local = sp * 32 + lane;
    const int grow = bm + row_local;
    const float* xr = resid + (size_t)grow * E_DIM;
    const float* bias = (const float*)(sm + SM_PAR);
    const float* gam  = (const float*)(sm + SM_PAR + 2048);
    const float* bet  = (const float*)(sm + SM_PAR + 4096);
    float* redp = (float*)(sm + SM_RED);

    // pass 1: stats over this warp's 128 cols
    float s = 0.f, ss = 0.f;
#pragma unroll 1
    for (int ch = 0; ch < 4; ++ch) {
        const int colb = q * 128 + ch * 32;
        uint32_t r[32];
        LDTM_X32(r, tmem + colb);
        TC_WAIT_LD();
#pragma unroll
        for (int c4 = 0; c4 < 8; ++c4) {
            const float4 xv = *(const float4*)(xr + colb + c4 * 4);
            const float4 bv = *(const float4*)(bias + colb + c4 * 4);
            float y0 = __uint_as_float(r[c4 * 4 + 0]) + xv.x + bv.x;
            float y1 = __uint_as_float(r[c4 * 4 + 1]) + xv.y + bv.y;
            float y2 = __uint_as_float(r[c4 * 4 + 2]) + xv.z + bv.z;
            float y3 = __uint_as_float(r[c4 * 4 + 3]) + xv.w + bv.w;
            s += y0 + y1 + y2 + y3;
            ss = fmaf(y0, y0, fmaf(y1, y1, fmaf(y2, y2, fmaf(y3, y3, ss))));
        }
    }
    redp[row_local * 4 + q] = s;
    redp[512 + row_local * 4 + q] = ss;
    __syncthreads();
    const float st  = redp[row_local * 4 + 0] + redp[row_local * 4 + 1] +
                      redp[row_local * 4 + 2] + redp[row_local * 4 + 3];
    const float sst = redp[512 + row_local * 4 + 0] + redp[512 + row_local * 4 + 1] +
                      redp[512 + row_local * 4 + 2] + redp[512 + row_local * 4 + 3];
    const float mu  = st * (1.0f / 512.0f);
    const float inv = rsqrtf(sst * (1.0f / 512.0f) - mu * mu + 1e-5f);

    // pass 2: normalize + store (coalesced via bounce)
    float* eb = (float*)(sm + SM_EP + w * 4608);  // [32][36]
    const int rbase = sp * 32;
#pragma unroll 1
    for (int ch = 0; ch < 4; ++ch) {
        const int colb = q * 128 + ch * 32;
        uint32_t r[32];
        LDTM_X32(r, tmem + colb);
        TC_WAIT_LD();
#pragma unroll
        for (int c4 = 0; c4 < 8; ++c4) {
            const float4 xv = *(const float4*)(xr + colb + c4 * 4);
            const float4 bv = *(const float4*)(bias + colb + c4 * 4);
            const float4 gv = *(const float4*)(gam + colb + c4 * 4);
            const float4 tv = *(const float4*)(bet + colb + c4 * 4);
            float4 o;
            o.x = (__uint_as_float(r[c4 * 4 + 0]) + xv.x + bv.x - mu) * inv * gv.x + tv.x;
            o.y = (__uint_as_float(r[c4 * 4 + 1]) + xv.y + bv.y - mu) * inv * gv.y + tv.y;
            o.z = (__uint_as_float(r[c4 * 4 + 2]) + xv.z + bv.z - mu) * inv * gv.z + tv.z;
            o.w = (__uint_as_float(r[c4 * 4 + 3]) + xv.w + bv.w - mu) * inv * gv.w + tv.w;
            *(float4*)(eb + lane * 36 + c4 * 4) = o;
        }
        if (do_fq && q == 0 && ch == 0) {
            const float4 o0 = *(const float4*)(eb + lane * 36);
            const float4 o1 = *(const float4*)(eb + lane * 36 + 4);
            float4 c0, c1;
            c0.x = __cosf(o0.x + thF[0]); c0.y = __cosf(o0.y + thF[1]);
            c0.z = __cosf(o0.z + thF[2]); c0.w = __cosf(o0.w + thF[3]);
            c1.x = __cosf(o1.x + thF[4]); c1.y = __cosf(o1.y + thF[5]);
            c1.z = __cosf(o1.z + thF[6]); c1.w = __cosf(o1.w + thF[7]);
            *(float4*)(g_fq + (size_t)grow * 8) = c0;
            *(float4*)(g_fq + (size_t)grow * 8 + 4) = c1;
        }
        __syncwarp();
#pragma unroll
        for (int j = 0; j < 32; ++j)
            dst[(size_t)(bm + rbase + j) * E_DIM + colb + lane] = eb[j * 36 + lane];
        __syncwarp();
    }
}

// ---------------- shared role loops ----------------
// MMA warp: 4-stage A ring, 2-stage B ring, dual commits
__device__ __forceinline__ void mma_role(uint32_t sb, uint32_t tmem, int NIT) {
    int pfa[4] = {0, 0, 0, 0}, pfb[2] = {0, 0};
    for (int it = 0; it < NIT; ++it) {
        const int sa = it & 3, s = it & 1;
        mbar_wait(sb + MB_FA + sa * 8, pfa[sa]); pfa[sa] ^= 1;
        mbar_wait(sb + MB_FB + s * 8, pfb[s]);   pfb[s] ^= 1;
        issue_tile(sb, SM_A0 + sa * 16384, SM_B0 + s * 65536, tmem, it == 0,
                   sb + MB_EB + s * 8, sb + MB_EA + sa * 8);
    }
    if (elect_one()) tc_commit(sb + MB_FIN);
}
// B copier role: 256 threads, ct in [0,256)
__device__ __forceinline__ void copyB_role(uint32_t sb, const char* bsrc, int NIT, int ct) {
    int pe[2] = {0, 0};
    for (int it = 0; it < NIT; ++it) {
        const int s = it & 1;
        if (it >= 2) { mbar_wait(sb + MB_EB + s * 8, pe[s]); pe[s] ^= 1; }
        const char* bs = bsrc + (size_t)it * 65536;
        const uint32_t d = sb + SM_B0 + s * 65536;
#pragma unroll
        for (int j = 0; j < 16; ++j) {
            const int g = ct + j * 256;
            cp16(d + g * 16, bs + (size_t)g * 16);
        }
        CP_COMMIT();
        CP_WAIT(0);
        fence_proxy_async_cta();
        mbar_arrive(sb + MB_FB + s * 8);
    }
}
#endif  // HAS_TCGEN05

// ================= GEMM1 + LN1 fused (3-role, 512 threads) =================
__global__ __launch_bounds__(512, 1)
void gemm1_tc(const float* __restrict__ x, const float* __restrict__ theta,
              const float* __restrict__ bc, const float* __restrict__ g1,
              const float* __restrict__ be1, const float* __restrict__ thF) {
#if HAS_TCGEN05
    extern __shared__ char sm[];
    const uint32_t sb = smem_u32(sm);
    const int t = threadIdx.x;
    const int bm = blockIdx.x * 128;

    if (t < 32) TC_ALLOC(sb + SM_TMEM, 512);
    if (t == 0) {
        for (int i = 0; i < 4; ++i) { mbar_init(sb + MB_FA + i * 8, 224); mbar_init(sb + MB_EA + i * 8, 1); }
        mbar_init(sb + MB_FB, 256); mbar_init(sb + MB_FB + 8, 256);
        mbar_init(sb + MB_EB, 1);   mbar_init(sb + MB_EB + 8, 1);
        mbar_init(sb + MB_FIN, 1);
    }
    if (t < 256) {
        ((float*)(sm + SM_PAR))[t] = bc[t];          ((float*)(sm + SM_PAR))[t + 256] = bc[t + 256];
        ((float*)(sm + SM_PAR + 2048))[t] = g1[t];   ((float*)(sm + SM_PAR + 2048))[t + 256] = g1[t + 256];
        ((float*)(sm + SM_PAR + 4096))[t] = be1[t];  ((float*)(sm + SM_PAR + 4096))[t + 256] = be1[t + 256];
        ((float*)(sm + SM_TH))[t] = theta[t];        ((float*)(sm + SM_TH))[t + 256] = theta[t + 256];
    }
    __syncthreads();

    uint32_t tmem;
    asm volatile("ld.shared.b32 %0, [%1];" : "=r"(tmem) : "r"(sb + SM_TMEM));
    const float* th_s = (const float*)(sm + SM_TH);
    const int NIT = E_DIM / 64;  // 8

    if (t < 32) {
        mma_role(sb, tmem, NIT);
    } else if (t < 288) {
        copyB_role(sb, (const char*)g_Wcp, NIT, t - 32);
    } else {
        // ---- A-gen (224 threads), 4-stage ring ----
        const int pt = t - 288;
        int pea[4] = {0, 0, 0, 0};
        for (int it = 0; it < NIT; ++it) {
            const int sa = it & 3;
            if (it >= 4) { mbar_wait(sb + MB_EA + sa * 8, pea[sa]); pea[sa] ^= 1; }
            const uint32_t Aoff = SM_A0 + sa * 16384;
            const int k0 = it * 64;
            for (int idx = pt; idx < 1024; idx += 224) {
                const int row = idx >> 3, q16 = idx & 7;
                const float* xp = x + (size_t)(bm + row) * E_DIM + k0 + q16 * 8;
                const float4 v0 = *(const float4*)xp;
                const float4 v1 = *(const float4*)(xp + 4);
                const float4 t0 = *(const float4*)(th_s + k0 + q16 * 8);
                const float4 t1 = *(const float4*)(th_s + k0 + q16 * 8 + 4);
                uint4 o;
                o.x = f2h2(__cosf(v0.x + t0.x), __cosf(v0.y + t0.y));
                o.y = f2h2(__cosf(v0.z + t0.z), __cosf(v0.w + t0.w));
                o.z = f2h2(__cosf(v1.x + t1.x), __cosf(v1.y + t1.y));
                o.w = f2h2(__cosf(v1.z + t1.z), __cosf(v1.w + t1.w));
                *(uint4*)(sm + Aoff + swz_off(row, q16)) = o;
            }
            fence_proxy_async_cta();
            mbar_arrive(sb + MB_FA + sa * 8);
        }
    }

    mbar_wait(sb + MB_FIN, 0);
    tc_fence_after();
    __syncthreads();

    epilogue_ln(sm, tmem, x, g_x1, bm, t, true, thF);

    __syncthreads();
    if (t < 32) { TC_RELINQ(); TC_DEALLOC(tmem, 512); }
#endif
}

// ================= GEMM2 + LN2 fused (3-role, 512 threads) =================
__global__ __launch_bounds__(512, 1)
void gemm2_tc(const float* __restrict__ W1, const float* __restrict__ b1,
              const float* __restrict__ b2, const float* __restrict__ g2,
              const float* __restrict__ be2, float* __restrict__ out) {
#if HAS_TCGEN05
    extern __shared__ char sm[];
    const uint32_t sb = smem_u32(sm);
    const int t = threadIdx.x;
    const int bm = blockIdx.x * 128;

    if (t < 32) TC_ALLOC(sb + SM_TMEM, 512);
    if (t == 0) {
        for (int i = 0; i < 4; ++i) { mbar_init(sb + MB_FA + i * 8, 224); mbar_init(sb + MB_EA + i * 8, 1); }
        mbar_init(sb + MB_FB, 256); mbar_init(sb + MB_FB + 8, 256);
        mbar_init(sb + MB_EB, 1);   mbar_init(sb + MB_EB + 8, 1);
        mbar_init(sb + MB_FIN, 1);
    }
    if (t < 256) {
        ((float*)(sm + SM_PAR))[t] = b2[t];          ((float*)(sm + SM_PAR))[t + 256] = b2[t + 256];
        ((float*)(sm + SM_PAR + 2048))[t] = g2[t];   ((float*)(sm + SM_PAR + 2048))[t + 256] = g2[t + 256];
        ((float*)(sm + SM_PAR + 4096))[t] = be2[t];  ((float*)(sm + SM_PAR + 4096))[t + 256] = be2[t + 256];
        ((float4*)(sm + SM_TH))[t] = ((const float4*)(g_fq + (size_t)bm * 8))[t];  // fq 4KB
    }
    __syncthreads();

    uint32_t tmem;
    asm volatile("ld.shared.b32 %0, [%1];" : "=r"(tmem) : "r"(sb + SM_TMEM));
    const int NIT = FFN_DIM / 64;  // 32

    if (t < 32) {
        mma_role(sb, tmem, NIT);
    } else if (t < 288) {
        copyB_role(sb, (const char*)g_W2p, NIT, t - 32);
    } else {
        // ---- A-gen (224 threads), 4-stage ring, register-prefetched W1 ----
        const int pt = t - 288;
        const int kl = pt & 31;      // k-col pair 0..31
        const int rg = pt >> 5;      // row group 0..6
        float4 wa0, wa1, wb0, wb1;
        float s0, s1;
        auto prefW = [&](int it) {
            const int k = it * 64 + kl * 2;
            wa0 = *(const float4*)(W1 + (size_t)k * 8);
            wa1 = *(const float4*)(W1 + (size_t)k * 8 + 4);
            wb0 = *(const float4*)(W1 + (size_t)(k + 1) * 8);
            wb1 = *(const float4*)(W1 + (size_t)(k + 1) * 8 + 4);
            s0 = b1[k]; s1 = b1[k + 1];
        };
        prefW(0);
        int pea[4] = {0, 0, 0, 0};
        for (int it = 0; it < NIT; ++it) {
            const int sa = it & 3;
            if (it >= 4) { mbar_wait(sb + MB_EA + sa * 8, pea[sa]); pea[sa] ^= 1; }
            const uint32_t Aoff = SM_A0 + sa * 16384;
            const float4 a0 = wa0, a1 = wa1, c0 = wb0, c1 = wb1;
            const float bv0 = s0, bv1 = s1;
            if (it + 1 < NIT) prefW(it + 1);   // LDGs fly during genA
            const uint32_t inner = (uint32_t)((kl & 3) * 4);
            const uint32_t q16g = (uint32_t)(kl >> 2);
#pragma unroll 2
            for (int r = rg; r < 128; r += 7) {
                const float4 f0 = *(const float4*)(sm + SM_TH + r * 32);
                const float4 f1 = *(const float4*)(sm + SM_TH + r * 32 + 16);
                float h0 = bv0, h1 = bv1;
                h0 = fmaf(f0.x, a0.x, h0); h0 = fmaf(f0.y, a0.y, h0);
                h0 = fmaf(f0.z, a0.z, h0); h0 = fmaf(f0.w, a0.w, h0);
                h0 = fmaf(f1.x, a1.x, h0); h0 = fmaf(f1.y, a1.y, h0);
                h0 = fmaf(f1.z, a1.z, h0); h0 = fmaf(f1.w, a1.w, h0);
                h1 = fmaf(f0.x, c0.x, h1); h1 = fmaf(f0.y, c0.y, h1);
                h1 = fmaf(f0.z, c0.z, h1); h1 = fmaf(f0.w, c0.w, h1);
                h1 = fmaf(f1.x, c1.x, h1); h1 = fmaf(f1.y, c1.y, h1);
                h1 = fmaf(f1.z, c1.z, h1); h1 = fmaf(f1.w, c1.w, h1);
                h0 = fmaxf(h0, 0.0f); h1 = fmaxf(h1, 0.0f);
                *(uint32_t*)(sm + Aoff + (uint32_t)(r * 128) +
                             (((q16g ^ (uint32_t)(r & 7)) * 16) + inner)) = f2h2(h0, h1);
            }
            fence_proxy_async_cta();
            mbar_arrive(sb + MB_FA + sa * 8);
        }
    }

    mbar_wait(sb + MB_FIN, 0);
    tc_fence_after();
    __syncthreads();

    epilogue_ln(sm, tmem, g_x1, out, bm, t, false, nullptr);

    __syncthreads();
    if (t < 32) { TC_RELINQ(); TC_DEALLOC(tmem, 512); }
#endif
}

// ================= launch =================
extern "C" void kernel_launch(void* const* d_in, const int* in_sizes, int n_in,
                              void* d_out, int out_size) {
    const float* x   = (const float*)d_in[0];
    const float* thA = (const float*)d_in[1];
    const float* Wc  = (const float*)d_in[2];
    const float* bc  = (const float*)d_in[3];
    const float* g1  = (const float*)d_in[4];
    const float* be1 = (const float*)d_in[5];
    const float* thF = (const float*)d_in[6];
    const float* W1  = (const float*)d_in[7];
    const float* b1  = (const float*)d_in[8];
    const float* W2  = (const float*)d_in[9];
    const float* b2  = (const float*)d_in[10];
    const float* g2  = (const float*)d_in[11];
    const float* be2 = (const float*)d_in[12];
    float* out = (float*)d_out;

    cudaFuncSetAttribute(gemm1_tc, cudaFuncAttributeMaxDynamicSharedMemorySize, SMEM_BYTES);
    cudaFuncSetAttribute(gemm2_tc, cudaFuncAttributeMaxDynamicSharedMemorySize, SMEM_BYTES);

    // pack weights (fp16 + SW128 smem image)
    repack_kernel<<<(512 * E_DIM / 8 + 255) / 256, 256>>>(Wc, E_DIM, 0);
    repack_kernel<<<(512 * FFN_DIM / 8 + 255) / 256, 256>>>(W2, FFN_DIM, 1);

    gemm1_tc<<<M_TOTAL / 128, 512, SMEM_BYTES>>>(x, thA, bc, g1, be1, thF);
    gemm2_tc<<<M_TOTAL / 128, 512, SMEM_BYTES>>>(W1, b1, b2, g2, be2, out);
}